// round 16
// baseline (speedup 1.0000x reference)
#include <cuda_runtime.h>
#include <cuda_fp16.h>
#include <cstdint>
#include <math.h>

// Problem constants
#define BATCH 8
#define CDIM 512
#define TDIM 1024
#define HEADS_ 8
#define EPS_ 1e-5f
#define RES_SCALE_ 0.7071067811865476f
// 64^-0.25 * sqrt(log2(e))  -> softmax uses exp2 directly
#define QK_SCALE_E 0.4246609001440095f

// Scratch (fp16 tensor-path, fp32 residual path)
__device__ float   g_xn   [BATCH * CDIM * TDIM];        // fp32 residual
__device__ __half  g_xnt  [BATCH * TDIM * CDIM];        // f16 [t,c]
__device__ __half  g_qkvb [BATCH * 3 * CDIM * TDIM];    // f16 [m,t] (q,v used)
__device__ __half  g_kt   [BATCH * HEADS_ * TDIM * 64]; // f16 [t,c] per head
__device__ __half  g_attnt[BATCH * TDIM * CDIM];        // f16 [t,c]
__device__ float   g_y    [BATCH * CDIM * TDIM];        // fp32 residual+proj
__device__ __half  g_wqkv [1536 * CDIM];                // f16 weights
__device__ __half  g_wproj[CDIM * CDIM];

// ===========================================================================
// Streams/events created at program load (before harness checkpoints).
// ===========================================================================
struct StreamRig {
    cudaStream_t sH = nullptr, sL = nullptr;
    cudaEvent_t  e0 = nullptr, eW = nullptr, eA = nullptr, eB = nullptr;
    bool ok = false;
    StreamRig() {
        int lo = 0, hi = 0;
        if (cudaDeviceGetStreamPriorityRange(&lo, &hi) != cudaSuccess) return;
        if (cudaStreamCreateWithPriority(&sH, cudaStreamNonBlocking, hi) != cudaSuccess) return;
        if (cudaStreamCreateWithPriority(&sL, cudaStreamNonBlocking, lo) != cudaSuccess) return;
        if (cudaEventCreateWithFlags(&e0, cudaEventDisableTiming) != cudaSuccess) return;
        if (cudaEventCreateWithFlags(&eW, cudaEventDisableTiming) != cudaSuccess) return;
        if (cudaEventCreateWithFlags(&eA, cudaEventDisableTiming) != cudaSuccess) return;
        if (cudaEventCreateWithFlags(&eB, cudaEventDisableTiming) != cudaSuccess) return;
        ok = true;
    }
};
static StreamRig g_rig;

// ===========================================================================
// mma.sync f16 m16n8k16 / ldmatrix / cp.async helpers
// ===========================================================================
__device__ __forceinline__ void mma_f16(float* d, const uint32_t* a,
                                        const uint32_t* b) {
    asm volatile(
        "mma.sync.aligned.m16n8k16.row.col.f32.f16.f16.f32 "
        "{%0,%1,%2,%3}, {%4,%5,%6,%7}, {%8,%9}, {%0,%1,%2,%3};"
        : "+f"(d[0]), "+f"(d[1]), "+f"(d[2]), "+f"(d[3])
        : "r"(a[0]), "r"(a[1]), "r"(a[2]), "r"(a[3]), "r"(b[0]), "r"(b[1]));
}
__device__ __forceinline__ void ldsm_x4(uint32_t* r, uint32_t addr) {
    asm volatile("ldmatrix.sync.aligned.m8n8.x4.shared.b16 {%0,%1,%2,%3}, [%4];"
        : "=r"(r[0]), "=r"(r[1]), "=r"(r[2]), "=r"(r[3]) : "r"(addr));
}
__device__ __forceinline__ uint32_t packhf(float lo, float hi) {
    __half2 h = __floats2half2_rn(lo, hi);
    return *(uint32_t*)&h;
}
__device__ __forceinline__ uint32_t h2ex2(float lo, float hi) {
    uint32_t u = packhf(lo, hi);
    asm("ex2.approx.f16x2 %0, %0;" : "+r"(u));
    return u;
}
__device__ __forceinline__ float ex2f(float x) {
    float y;
    asm("ex2.approx.ftz.f32 %0, %1;" : "=f"(y) : "f"(x));
    return y;
}
__device__ __forceinline__ void cp16(void* smem, const void* gmem) {
    uint32_t s = (uint32_t)__cvta_generic_to_shared(smem);
    asm volatile("cp.async.cg.shared.global [%0], [%1], 16;" :: "r"(s), "l"(gmem));
}
#define CP_COMMIT() asm volatile("cp.async.commit_group;" ::: "memory")
#define CP_WAIT1()  asm volatile("cp.async.wait_group 1;" ::: "memory")
#define CP_WAIT0()  asm volatile("cp.async.wait_group 0;" ::: "memory")

// ===========================================================================
// Weight fp32 -> f16 conversion
// ===========================================================================
__global__ __launch_bounds__(256) void wconv_kernel(const float* __restrict__ qw,
                                                    const float* __restrict__ pw)
{
    const int NQ = 1536 * CDIM / 4;
    const int NP = CDIM * CDIM / 4;
    int i = blockIdx.x * 256 + threadIdx.x;
    if (i < NQ) {
        float4 v = ((const float4*)qw)[i];
        uint2 o; o.x = packhf(v.x, v.y); o.y = packhf(v.z, v.w);
        ((uint2*)g_wqkv)[i] = o;
    } else if (i < NQ + NP) {
        int j = i - NQ;
        float4 v = ((const float4*)pw)[j];
        uint2 o; o.x = packhf(v.x, v.y); o.y = packhf(v.z, v.w);
        ((uint2*)g_wproj)[j] = o;
    }
}

// ===========================================================================
// Block-wide (256 threads) sum + sumsq reduction
// ===========================================================================
__device__ __forceinline__ void block_reduce2(float& s, float& s2, float* sh)
{
    #pragma unroll
    for (int o = 16; o > 0; o >>= 1) {
        s  += __shfl_down_sync(0xffffffffu, s,  o);
        s2 += __shfl_down_sync(0xffffffffu, s2, o);
    }
    int warp = threadIdx.x >> 5, lane = threadIdx.x & 31;
    if (lane == 0) { sh[warp] = s; sh[8 + warp] = s2; }
    __syncthreads();
    if (threadIdx.x < 32) {
        s  = (lane < 8) ? sh[lane]     : 0.f;
        s2 = (lane < 8) ? sh[8 + lane] : 0.f;
        #pragma unroll
        for (int o = 4; o > 0; o >>= 1) {
            s  += __shfl_down_sync(0xffffffffu, s,  o);
            s2 += __shfl_down_sync(0xffffffffu, s2, o);
        }
        if (lane == 0) { sh[0] = s; sh[1] = s2; }
    }
    __syncthreads();
    s = sh[0]; s2 = sh[1];
}

// ===========================================================================
// GroupNorm #1 (affine): x -> g_xn (fp32 [c,t]) AND g_xnt (f16 [t,c])
// ===========================================================================
__global__ __launch_bounds__(256) void gn1_kernel(const float* __restrict__ x,
                                                  const float* __restrict__ w,
                                                  const float* __restrict__ bia,
                                                  int blk0)
{
    __shared__ float sh[16];
    int blk = blockIdx.x + blk0;
    int b = blk >> 5, g = blk & 31;
    size_t off = ((size_t)b * CDIM + (size_t)g * 16) * TDIM;
    const float4* xp = (const float4*)(x + off);
    int tid = threadIdx.x;

    float4 v[16];
    float s = 0.f, s2 = 0.f;
    #pragma unroll
    for (int j = 0; j < 16; j++) {
        float4 a = xp[j * 256 + tid];
        v[j] = a;
        s  += a.x + a.y + a.z + a.w;
        s2 += a.x*a.x + a.y*a.y + a.z*a.z + a.w*a.w;
    }
    block_reduce2(s, s2, sh);
    float mean = s * (1.f / 16384.f);
    float var  = s2 * (1.f / 16384.f) - mean * mean;
    float rstd = rsqrtf(var + EPS_);

    float scl[16], shf[16];
    #pragma unroll
    for (int j = 0; j < 16; j++) {
        int ch = g * 16 + j;
        scl[j] = w[ch] * rstd;
        shf[j] = bia[ch] - mean * scl[j];
    }

    float4* op = (float4*)(g_xn + off);
    #pragma unroll
    for (int j = 0; j < 16; j++) {
        float4 a = v[j], o;
        o.x = a.x * scl[j] + shf[j]; o.y = a.y * scl[j] + shf[j];
        o.z = a.z * scl[j] + shf[j]; o.w = a.w * scl[j] + shf[j];
        v[j] = o;
        op[j * 256 + tid] = o;
    }

    __half* xt = g_xnt + ((size_t)b * TDIM + (size_t)tid * 4) * CDIM + g * 16;
    #pragma unroll
    for (int u = 0; u < 4; u++) {
        uint32_t tmp[8];
        #pragma unroll
        for (int j2 = 0; j2 < 8; j2++)
            tmp[j2] = packhf(((const float*)&v[j2*2])[u],
                             ((const float*)&v[j2*2+1])[u]);
        uint4* r = (uint4*)(xt + (size_t)u * CDIM);
        r[0] = *(uint4*)(tmp);
        r[1] = *(uint4*)(tmp + 4);
    }
}

// ===========================================================================
// f16 mma GEMM: 128x128 CTA tile, 128 threads (4 warps, 2x2), warp tile
// 64x64 -> each ldsm fragment feeds 4 MMAs (ratio 4.0). KC=64, 2-stage.
// MODE 0: Bt=g_xnt,   out -> g_qkvb (q,v) + g_kt (k transposed), f16
// MODE 1: Bt=g_attnt, out -> g_y = RES_SCALE*g_xn + proj + bias (fp32)
// ===========================================================================
#define KC 64
#define BSTR 72                    // f16 row stride (144 B)
#define GITER (CDIM / KC)          // 8
#define GSTAGE (128 * BSTR)
#define GEMM_SMEM (2 * GSTAGE * 2 * 2)   // 73728 B

template <int MODE>
__global__ __launch_bounds__(128) void mma_gemm(const float* __restrict__ bias,
                                                int z0)
{
    extern __shared__ __half smg[];
    __half* As = smg;
    __half* Bs = smg + 2 * GSTAGE;

    const int tid  = threadIdx.x;
    const int lane = tid & 31;
    const int wrp  = tid >> 5;
    const int g    = lane >> 2, tig = lane & 3;
    const int m0w  = (wrp & 1) * 64;
    const int n0w  = (wrp >> 1) * 64;

    const int mat = lane >> 3, rowl = lane & 7;
    const uint32_t roffA = ((mat & 1) * 8 + rowl) * 144 + (mat >> 1) * 16;
    const uint32_t roffB = ((mat >> 1) * 8 + rowl) * 144 + (mat & 1) * 16;
    const uint32_t asB = (uint32_t)__cvta_generic_to_shared(As);
    const uint32_t bsB = (uint32_t)__cvta_generic_to_shared(Bs);

    const int z    = blockIdx.z + z0;
    const int row0 = blockIdx.y * 128;
    const int col0 = blockIdx.x * 128;
    const __half* Aw = (MODE == 0 ? g_wqkv : g_wproj) + (size_t)row0 * CDIM;
    const __half* Bb = (MODE == 0 ? g_xnt : g_attnt)
                     + (size_t)z * TDIM * CDIM + (size_t)col0 * CDIM;

    float acc[4][8][4];
    #pragma unroll
    for (int mt = 0; mt < 4; mt++)
        #pragma unroll
        for (int nt = 0; nt < 8; nt++)
            #pragma unroll
            for (int j = 0; j < 4; j++) acc[mt][nt][j] = 0.f;

    auto load_stage = [&](int st, int k0) {
        __half* pa = As + st * GSTAGE;
        __half* pb = Bs + st * GSTAGE;
        #pragma unroll
        for (int s = 0; s < 8; s++) {
            int i = tid + s * 128;
            int row = i >> 3, kc = (i & 7) * 8;
            cp16(pa + row * BSTR + kc, Aw + (size_t)row * CDIM + k0 + kc);
            cp16(pb + row * BSTR + kc, Bb + (size_t)row * CDIM + k0 + kc);
        }
    };

    load_stage(0, 0);  CP_COMMIT();

    #pragma unroll 1
    for (int it = 0; it < GITER; it++) {
        int st = it & 1;
        if (it + 1 < GITER) {
            load_stage(st ^ 1, (it + 1) * KC);
            CP_COMMIT();
            CP_WAIT1();
        } else {
            CP_WAIT0();
        }
        __syncthreads();

        const uint32_t aSt = asB + st * GSTAGE * 2;
        const uint32_t bSt = bsB + st * GSTAGE * 2;
        #pragma unroll
        for (int ks = 0; ks < 4; ks++) {
            uint32_t aF[4][4];
            #pragma unroll
            for (int mt = 0; mt < 4; mt++)
                ldsm_x4(aF[mt], aSt + (uint32_t)(m0w + mt * 16) * 144 + roffA + ks * 32);
            #pragma unroll
            for (int p = 0; p < 4; p++) {
                uint32_t bF[4];
                ldsm_x4(bF, bSt + (uint32_t)(n0w + p * 16) * 144 + roffB + ks * 32);
                #pragma unroll
                for (int mt = 0; mt < 4; mt++) {
                    mma_f16(acc[mt][2*p],   aF[mt], bF);
                    mma_f16(acc[mt][2*p+1], aF[mt], bF + 2);
                }
            }
        }
        __syncthreads();
    }

    // Epilogue
    #pragma unroll
    for (int mt = 0; mt < 4; mt++) {
        #pragma unroll
        for (int rr = 0; rr < 2; rr++) {
            int m = row0 + m0w + mt * 16 + g + rr * 8;
            float bv = bias[m];
            if (MODE == 0) {
                int head = m / 192, r = m % 192;
                float scale = (r < 128) ? QK_SCALE_E : 1.f;
                if (r >= 64 && r < 128) {
                    __half* kb = g_kt + (((size_t)(z * 8 + head)) << 10) * 64 + (r - 64);
                    #pragma unroll
                    for (int nt = 0; nt < 8; nt++) {
                        int t = col0 + n0w + nt * 8 + 2 * tig;
                        float x0 = (acc[mt][nt][rr * 2 + 0] + bv) * scale;
                        float x1 = (acc[mt][nt][rr * 2 + 1] + bv) * scale;
                        kb[(size_t)t * 64]       = __float2half(x0);
                        kb[(size_t)(t + 1) * 64] = __float2half(x1);
                    }
                } else {
                    __half* crow = g_qkvb + ((size_t)z * 1536 + m) * TDIM
                                 + col0 + n0w;
                    #pragma unroll
                    for (int nt = 0; nt < 8; nt++) {
                        uint32_t p = packhf((acc[mt][nt][rr*2+0] + bv) * scale,
                                            (acc[mt][nt][rr*2+1] + bv) * scale);
                        *(uint32_t*)(crow + nt * 8 + 2 * tig) = p;
                    }
                }
            } else {
                size_t rowoff = ((size_t)z * CDIM + m) * TDIM + col0 + n0w;
                const float* xnrow = g_xn + rowoff;
                float* crow = g_y + rowoff;
                #pragma unroll
                for (int nt = 0; nt < 8; nt++) {
                    float2 xv = *(const float2*)(xnrow + nt * 8 + 2 * tig);
                    float2 o;
                    o.x = acc[mt][nt][rr * 2 + 0] + bv + RES_SCALE_ * xv.x;
                    o.y = acc[mt][nt][rr * 2 + 1] + bv + RES_SCALE_ * xv.y;
                    *(float2*)(crow + nt * 8 + 2 * tig) = o;
                }
            }
        }
    }
}

// ===========================================================================
// Flash attention, 256-query CTA: warp owns 32 queries (two 16-q sub-tiles)
// sharing each K/V ldmatrix fragment. f16 mma + f16x2 exp2 + ones-MMA l.
// 4-stage ring, sync per 2 tiles.
// ===========================================================================
#define KST 72                      // f16 row stride (144 B)
#define KVSTAGE (64 * KST)
#define ASTAGES 4
#define ATTN_SMEM (2 * ASTAGES * KVSTAGE * 2)   // 73728 B

__global__ __launch_bounds__(256) void attn_mma_kernel(int bh0)
{
    extern __shared__ __half sma[];
    __half* Ks = sma;                         // 4 stages
    __half* Vs = sma + ASTAGES * KVSTAGE;     // 4 stages

    const int tid  = threadIdx.x;
    const int lane = tid & 31;
    const int wrp  = tid >> 5;
    const int g    = lane >> 2, tig = lane & 3;
    const int ql   = wrp * 32;               // warp query base (32 q)

    const int mat = lane >> 3, rowl = lane & 7;
    const uint32_t roff = ((mat >> 1) * 8 + rowl) * (KST * 2) + (mat & 1) * 16;
    const uint32_t ksB = (uint32_t)__cvta_generic_to_shared(Ks);
    const uint32_t vsB = (uint32_t)__cvta_generic_to_shared(Vs);

    const int bh = blockIdx.y + bh0;
    const int b = bh >> 3, head = bh & 7;
    const int q0 = blockIdx.x * 256;

    const __half* qp  = g_qkvb + ((size_t)b * 1536 + head * 192) * TDIM;
    const __half* vp  = qp + (size_t)128 * TDIM;
    const __half* ktp = g_kt + (((size_t)(b * 8 + head)) << 10) * 64;

    auto load_stage = [&](int st, int s0) {
        __half* pk = Ks + st * KVSTAGE;
        __half* pv = Vs + st * KVSTAGE;
        #pragma unroll
        for (int s = 0; s < 2; s++) {
            int i = tid + s * 256;
            int row = i >> 3, ch8 = (i & 7) * 8;
            cp16(pk + row * KST + ch8, ktp + (size_t)(s0 + row) * 64 + ch8);
            cp16(pv + row * KST + ch8, vp + (size_t)row * TDIM + s0 + ch8);
        }
    };

    // Q fragments for both 16-q sub-tiles, register-resident
    uint32_t aQ[2][4][4];
    #pragma unroll
    for (int s = 0; s < 2; s++) {
        int tq0 = q0 + ql + s * 16 + g;
        #pragma unroll
        for (int kk = 0; kk < 4; kk++) {
            int c0 = kk * 16 + 2 * tig;
            aQ[s][kk][0] = packhf(__half2float(qp[(size_t)(c0)     * TDIM + tq0]),
                                  __half2float(qp[(size_t)(c0 + 1) * TDIM + tq0]));
            aQ[s][kk][1] = packhf(__half2float(qp[(size_t)(c0)     * TDIM + tq0 + 8]),
                                  __half2float(qp[(size_t)(c0 + 1) * TDIM + tq0 + 8]));
            aQ[s][kk][2] = packhf(__half2float(qp[(size_t)(c0 + 8) * TDIM + tq0]),
                                  __half2float(qp[(size_t)(c0 + 9) * TDIM + tq0]));
            aQ[s][kk][3] = packhf(__half2float(qp[(size_t)(c0 + 8) * TDIM + tq0 + 8]),
                                  __half2float(qp[(size_t)(c0 + 9) * TDIM + tq0 + 8]));
        }
    }

    load_stage(0, 0);   CP_COMMIT();
    load_stage(1, 64);  CP_COMMIT();

    float oacc[2][8][4];
    #pragma unroll
    for (int s = 0; s < 2; s++)
        #pragma unroll
        for (int ct = 0; ct < 8; ct++)
            #pragma unroll
            for (int j = 0; j < 4; j++) oacc[s][ct][j] = 0.f;
    float lacc[2][4] = {{0.f,0.f,0.f,0.f},{0.f,0.f,0.f,0.f}};
    float m0[2] = {-1e30f, -1e30f}, m1[2] = {-1e30f, -1e30f};
    const uint32_t ONES2 = 0x3C003C00u;
    uint32_t onesF[2] = {ONES2, ONES2};

    #pragma unroll 1
    for (int kt = 0; kt < 16; kt++) {
        int st = kt % ASTAGES;
        if ((kt & 1) == 0) {
            CP_WAIT0();
            __syncthreads();
        }
        if (kt + 2 < 16) {
            load_stage((kt + 2) % ASTAGES, (kt + 2) * 64);
            CP_COMMIT();
        }

        const uint32_t kSt = ksB + st * KVSTAGE * 2;
        const uint32_t vSt = vsB + st * KVSTAGE * 2;

        // S = Q^T K : [32q][64s]; each K fragment feeds BOTH sub-tiles
        float sacc[2][8][4];
        #pragma unroll
        for (int s = 0; s < 2; s++)
            #pragma unroll
            for (int nt = 0; nt < 8; nt++)
                #pragma unroll
                for (int j = 0; j < 4; j++) sacc[s][nt][j] = 0.f;
        #pragma unroll
        for (int kk = 0; kk < 4; kk++) {
            #pragma unroll
            for (int p = 0; p < 4; p++) {
                uint32_t bF[4];
                ldsm_x4(bF, kSt + p * (16 * KST * 2) + roff + kk * 32);
                mma_f16(sacc[0][2*p],   aQ[0][kk], bF);
                mma_f16(sacc[0][2*p+1], aQ[0][kk], bF + 2);
                mma_f16(sacc[1][2*p],   aQ[1][kk], bF);
                mma_f16(sacc[1][2*p+1], aQ[1][kk], bF + 2);
            }
        }

        // online softmax per sub-tile (exp2 domain)
        #pragma unroll
        for (int s = 0; s < 2; s++) {
            float rmax0 = -1e30f, rmax1 = -1e30f;
            #pragma unroll
            for (int nt = 0; nt < 8; nt++) {
                rmax0 = fmaxf(rmax0, fmaxf(sacc[s][nt][0], sacc[s][nt][1]));
                rmax1 = fmaxf(rmax1, fmaxf(sacc[s][nt][2], sacc[s][nt][3]));
            }
            #pragma unroll
            for (int o = 1; o <= 2; o <<= 1) {
                rmax0 = fmaxf(rmax0, __shfl_xor_sync(0xffffffffu, rmax0, o));
                rmax1 = fmaxf(rmax1, __shfl_xor_sync(0xffffffffu, rmax1, o));
            }
            float mn0 = fmaxf(m0[s], rmax0), mn1 = fmaxf(m1[s], rmax1);
            float corr0 = ex2f(m0[s] - mn0), corr1 = ex2f(m1[s] - mn1);
            m0[s] = mn0; m1[s] = mn1;
            lacc[s][0] *= corr0; lacc[s][2] *= corr1;
            #pragma unroll
            for (int ct = 0; ct < 8; ct++) {
                oacc[s][ct][0] *= corr0; oacc[s][ct][1] *= corr0;
                oacc[s][ct][2] *= corr1; oacc[s][ct][3] *= corr1;
            }
        }

        // O += P V^T; each V fragment feeds BOTH sub-tiles
        #pragma unroll
        for (int kk = 0; kk < 4; kk++) {
            uint32_t aP0[4], aP1[4];
            aP0[0] = h2ex2(sacc[0][2*kk][0]   - m0[0], sacc[0][2*kk][1]   - m0[0]);
            aP0[1] = h2ex2(sacc[0][2*kk][2]   - m1[0], sacc[0][2*kk][3]   - m1[0]);
            aP0[2] = h2ex2(sacc[0][2*kk+1][0] - m0[0], sacc[0][2*kk+1][1] - m0[0]);
            aP0[3] = h2ex2(sacc[0][2*kk+1][2] - m1[0], sacc[0][2*kk+1][3] - m1[0]);
            aP1[0] = h2ex2(sacc[1][2*kk][0]   - m0[1], sacc[1][2*kk][1]   - m0[1]);
            aP1[1] = h2ex2(sacc[1][2*kk][2]   - m1[1], sacc[1][2*kk][3]   - m1[1]);
            aP1[2] = h2ex2(sacc[1][2*kk+1][0] - m0[1], sacc[1][2*kk+1][1] - m0[1]);
            aP1[3] = h2ex2(sacc[1][2*kk+1][2] - m1[1], sacc[1][2*kk+1][3] - m1[1]);
            mma_f16(lacc[0], aP0, onesF);
            mma_f16(lacc[1], aP1, onesF);
            #pragma unroll
            for (int p = 0; p < 4; p++) {
                uint32_t bF[4];
                ldsm_x4(bF, vSt + p * (16 * KST * 2) + roff + kk * 32);
                mma_f16(oacc[0][2*p],   aP0, bF);
                mma_f16(oacc[0][2*p+1], aP0, bF + 2);
                mma_f16(oacc[1][2*p],   aP1, bF);
                mma_f16(oacc[1][2*p+1], aP1, bF + 2);
            }
        }
    }

    // normalize + write both sub-tiles
    #pragma unroll
    for (int s = 0; s < 2; s++) {
        float inv0 = 1.f / lacc[s][0], inv1 = 1.f / lacc[s][2];
        int tq = q0 + ql + s * 16 + g;
        __half* orow0 = g_attnt + ((size_t)b * TDIM + tq)     * CDIM + head * 64;
        __half* orow1 = g_attnt + ((size_t)b * TDIM + tq + 8) * CDIM + head * 64;
        #pragma unroll
        for (int ct = 0; ct < 8; ct++) {
            *(uint32_t*)(orow0 + ct * 8 + 2 * tig) =
                packhf(oacc[s][ct][0] * inv0, oacc[s][ct][1] * inv0);
            *(uint32_t*)(orow1 + ct * 8 + 2 * tig) =
                packhf(oacc[s][ct][2] * inv1, oacc[s][ct][3] * inv1);
        }
    }
}

// ===========================================================================
// GroupNorm #2 (no affine) over g_y -> d_out. blk0: block offset.
// ===========================================================================
__global__ __launch_bounds__(256) void gn2_kernel(float* __restrict__ out, int blk0)
{
    __shared__ float sh[16];
    int blk = blockIdx.x + blk0;
    int b = blk >> 5, g = blk & 31;
    size_t off = ((size_t)b * CDIM + (size_t)g * 16) * TDIM;
    const float4* yp = (const float4*)(g_y + off);
    int tid = threadIdx.x;

    float4 v[16];
    float s = 0.f, s2 = 0.f;
    #pragma unroll
    for (int j = 0; j < 16; j++) {
        float4 y = yp[j * 256 + tid];
        v[j] = y;
        s  += y.x + y.y + y.z + y.w;
        s2 += y.x*y.x + y.y*y.y + y.z*y.z + y.w*y.w;
    }
    block_reduce2(s, s2, sh);
    float mean = s * (1.f / 16384.f);
    float var  = s2 * (1.f / 16384.f) - mean * mean;
    float rstd = rsqrtf(var + EPS_);

    float4* op = (float4*)(out + off);
    #pragma unroll
    for (int j = 0; j < 16; j++) {
        float4 y = v[j], o;
        o.x = (y.x - mean) * rstd; o.y = (y.y - mean) * rstd;
        o.z = (y.z - mean) * rstd; o.w = (y.w - mean) * rstd;
        op[j * 256 + tid] = o;
    }
}

// ===========================================================================
extern "C" void kernel_launch(void* const* d_in, const int* in_sizes, int n_in,
                              void* d_out, int out_size)
{
    const float* x      = (const float*)d_in[0];
    const float* gn_w   = (const float*)d_in[1];
    const float* gn_b   = (const float*)d_in[2];
    const float* qkv_w  = (const float*)d_in[3];
    const float* qkv_b  = (const float*)d_in[4];
    const float* proj_w = (const float*)d_in[5];
    const float* proj_b = (const float*)d_in[6];
    float* out = (float*)d_out;

    cudaFuncSetAttribute(mma_gemm<0>, cudaFuncAttributeMaxDynamicSharedMemorySize, GEMM_SMEM);
    cudaFuncSetAttribute(mma_gemm<1>, cudaFuncAttributeMaxDynamicSharedMemorySize, GEMM_SMEM);
    cudaFuncSetAttribute(attn_mma_kernel, cudaFuncAttributeMaxDynamicSharedMemorySize, ATTN_SMEM);

    const int WBLK = (1536 * CDIM / 4 + CDIM * CDIM / 4 + 255) / 256;

    if (g_rig.ok) {
        cudaStream_t sH = g_rig.sH, sL = g_rig.sL;
        // fork from capture (legacy) stream
        cudaEventRecord(g_rig.e0, 0);
        cudaStreamWaitEvent(sH, g_rig.e0, 0);
        cudaStreamWaitEvent(sL, g_rig.e0, 0);

        // chain B starts with wconv + gn1B (both independent of chain A)
        wconv_kernel<<<WBLK, 256, 0, sL>>>(qkv_w, proj_w);
        cudaEventRecord(g_rig.eW, sL);
        gn1_kernel<<<128, 256, 0, sL>>>(x, gn_w, gn_b, 128);  // batches 4-7

        // chain A: gn1A -> qkvA -> attnA -> projA -> gn2A
        gn1_kernel<<<128, 256, 0, sH>>>(x, gn_w, gn_b, 0);    // batches 0-3
        cudaStreamWaitEvent(sH, g_rig.eW, 0);                 // weights ready
        mma_gemm<0><<<dim3(8, 12, 4), 128, GEMM_SMEM, sH>>>(qkv_b, 0);
        attn_mma_kernel<<<dim3(4, 32), 256, ATTN_SMEM, sH>>>(0);
        mma_gemm<1><<<dim3(8, 4, 4), 128, GEMM_SMEM, sH>>>(proj_b, 0);
        gn2_kernel<<<128, 256, 0, sH>>>(out, 0);
        cudaEventRecord(g_rig.eA, sH);

        // chain B continues (fully concurrent with chain A)
        mma_gemm<0><<<dim3(8, 12, 4), 128, GEMM_SMEM, sL>>>(qkv_b, 4);
        attn_mma_kernel<<<dim3(4, 32), 256, ATTN_SMEM, sL>>>(32);
        mma_gemm<1><<<dim3(8, 4, 4), 128, GEMM_SMEM, sL>>>(proj_b, 4);
        gn2_kernel<<<128, 256, 0, sL>>>(out, 128);
        cudaEventRecord(g_rig.eB, sL);

        // rejoin capture stream
        cudaStreamWaitEvent((cudaStream_t)0, g_rig.eA, 0);
        cudaStreamWaitEvent((cudaStream_t)0, g_rig.eB, 0);
    } else {
        // serial fallback
        wconv_kernel<<<WBLK, 256>>>(qkv_w, proj_w);
        gn1_kernel<<<BATCH * 32, 256>>>(x, gn_w, gn_b, 0);
        mma_gemm<0><<<dim3(8, 12, 8), 128, GEMM_SMEM>>>(qkv_b, 0);
        attn_mma_kernel<<<dim3(4, 64), 256, ATTN_SMEM>>>(0);
        mma_gemm<1><<<dim3(8, 4, 8), 128, GEMM_SMEM>>>(proj_b, 0);
        gn2_kernel<<<256, 256>>>(out, 0);
    }
}

// round 17
// speedup vs baseline: 1.0857x; 1.0857x over previous
#include <cuda_runtime.h>
#include <cuda_fp16.h>
#include <cstdint>
#include <math.h>

// Problem constants
#define BATCH 8
#define CDIM 512
#define TDIM 1024
#define HEADS_ 8
#define EPS_ 1e-5f
#define RES_SCALE_ 0.7071067811865476f
// 64^-0.25 * sqrt(log2(e))  -> softmax uses exp2 directly
#define QK_SCALE_E 0.4246609001440095f

// Scratch (fp16 tensor-path, fp32 residual path)
__device__ float   g_xn   [BATCH * CDIM * TDIM];        // fp32 residual
__device__ __half  g_xnt  [BATCH * TDIM * CDIM];        // f16 [t,c]
__device__ __half  g_qkvb [BATCH * 3 * CDIM * TDIM];    // f16 [m,t] (q,v used)
__device__ __half  g_kt   [BATCH * HEADS_ * TDIM * 64]; // f16 [t,c] per head
__device__ __half  g_attnt[BATCH * TDIM * CDIM];        // f16 [t,c]
__device__ float   g_y    [BATCH * CDIM * TDIM];        // fp32 residual+proj
__device__ __half  g_wqkv [1536 * CDIM];                // f16 weights
__device__ __half  g_wproj[CDIM * CDIM];

// ===========================================================================
// Streams/events created at program load (before harness checkpoints).
// ===========================================================================
struct StreamRig {
    cudaStream_t sH = nullptr, sL = nullptr;
    cudaEvent_t  e0 = nullptr, eW = nullptr, eW2 = nullptr,
                 eA = nullptr, eB = nullptr;
    bool ok = false;
    StreamRig() {
        int lo = 0, hi = 0;
        if (cudaDeviceGetStreamPriorityRange(&lo, &hi) != cudaSuccess) return;
        if (cudaStreamCreateWithPriority(&sH, cudaStreamNonBlocking, hi) != cudaSuccess) return;
        if (cudaStreamCreateWithPriority(&sL, cudaStreamNonBlocking, lo) != cudaSuccess) return;
        if (cudaEventCreateWithFlags(&e0,  cudaEventDisableTiming) != cudaSuccess) return;
        if (cudaEventCreateWithFlags(&eW,  cudaEventDisableTiming) != cudaSuccess) return;
        if (cudaEventCreateWithFlags(&eW2, cudaEventDisableTiming) != cudaSuccess) return;
        if (cudaEventCreateWithFlags(&eA,  cudaEventDisableTiming) != cudaSuccess) return;
        if (cudaEventCreateWithFlags(&eB,  cudaEventDisableTiming) != cudaSuccess) return;
        ok = true;
    }
};
static StreamRig g_rig;

// ===========================================================================
// mma.sync f16 m16n8k16 / ldmatrix / cp.async helpers
// ===========================================================================
__device__ __forceinline__ void mma_f16(float* d, const uint32_t* a,
                                        const uint32_t* b) {
    asm volatile(
        "mma.sync.aligned.m16n8k16.row.col.f32.f16.f16.f32 "
        "{%0,%1,%2,%3}, {%4,%5,%6,%7}, {%8,%9}, {%0,%1,%2,%3};"
        : "+f"(d[0]), "+f"(d[1]), "+f"(d[2]), "+f"(d[3])
        : "r"(a[0]), "r"(a[1]), "r"(a[2]), "r"(a[3]), "r"(b[0]), "r"(b[1]));
}
__device__ __forceinline__ void ldsm_x4(uint32_t* r, uint32_t addr) {
    asm volatile("ldmatrix.sync.aligned.m8n8.x4.shared.b16 {%0,%1,%2,%3}, [%4];"
        : "=r"(r[0]), "=r"(r[1]), "=r"(r[2]), "=r"(r[3]) : "r"(addr));
}
__device__ __forceinline__ uint32_t packhf(float lo, float hi) {
    __half2 h = __floats2half2_rn(lo, hi);
    return *(uint32_t*)&h;
}
__device__ __forceinline__ uint32_t h2ex2(float lo, float hi) {
    uint32_t u = packhf(lo, hi);
    asm("ex2.approx.f16x2 %0, %0;" : "+r"(u));
    return u;
}
__device__ __forceinline__ float ex2f(float x) {
    float y;
    asm("ex2.approx.ftz.f32 %0, %1;" : "=f"(y) : "f"(x));
    return y;
}
__device__ __forceinline__ void cp16(void* smem, const void* gmem) {
    uint32_t s = (uint32_t)__cvta_generic_to_shared(smem);
    asm volatile("cp.async.cg.shared.global [%0], [%1], 16;" :: "r"(s), "l"(gmem));
}
#define CP_COMMIT() asm volatile("cp.async.commit_group;" ::: "memory")
#define CP_WAIT0()  asm volatile("cp.async.wait_group 0;" ::: "memory")

// ===========================================================================
// Weight fp32 -> f16 conversion (split: qkv first, proj later)
// ===========================================================================
__global__ __launch_bounds__(256) void wconv_qkv_kernel(const float* __restrict__ qw)
{
    int i = blockIdx.x * 256 + threadIdx.x;
    if (i < 1536 * CDIM / 4) {
        float4 v = ((const float4*)qw)[i];
        uint2 o; o.x = packhf(v.x, v.y); o.y = packhf(v.z, v.w);
        ((uint2*)g_wqkv)[i] = o;
    }
}
__global__ __launch_bounds__(256) void wconv_proj_kernel(const float* __restrict__ pw)
{
    int i = blockIdx.x * 256 + threadIdx.x;
    if (i < CDIM * CDIM / 4) {
        float4 v = ((const float4*)pw)[i];
        uint2 o; o.x = packhf(v.x, v.y); o.y = packhf(v.z, v.w);
        ((uint2*)g_wproj)[i] = o;
    }
}

// ===========================================================================
// Block-wide (256 threads) sum + sumsq reduction
// ===========================================================================
__device__ __forceinline__ void block_reduce2(float& s, float& s2, float* sh)
{
    #pragma unroll
    for (int o = 16; o > 0; o >>= 1) {
        s  += __shfl_down_sync(0xffffffffu, s,  o);
        s2 += __shfl_down_sync(0xffffffffu, s2, o);
    }
    int warp = threadIdx.x >> 5, lane = threadIdx.x & 31;
    if (lane == 0) { sh[warp] = s; sh[8 + warp] = s2; }
    __syncthreads();
    if (threadIdx.x < 32) {
        s  = (lane < 8) ? sh[lane]     : 0.f;
        s2 = (lane < 8) ? sh[8 + lane] : 0.f;
        #pragma unroll
        for (int o = 4; o > 0; o >>= 1) {
            s  += __shfl_down_sync(0xffffffffu, s,  o);
            s2 += __shfl_down_sync(0xffffffffu, s2, o);
        }
        if (lane == 0) { sh[0] = s; sh[1] = s2; }
    }
    __syncthreads();
    s = sh[0]; s2 = sh[1];
}

// ===========================================================================
// GroupNorm #1 (affine): x -> g_xn (fp32 [c,t]) AND g_xnt (f16 [t,c])
// ===========================================================================
__global__ __launch_bounds__(256) void gn1_kernel(const float* __restrict__ x,
                                                  const float* __restrict__ w,
                                                  const float* __restrict__ bia,
                                                  int blk0)
{
    __shared__ float sh[16];
    int blk = blockIdx.x + blk0;
    int b = blk >> 5, g = blk & 31;
    size_t off = ((size_t)b * CDIM + (size_t)g * 16) * TDIM;
    const float4* xp = (const float4*)(x + off);
    int tid = threadIdx.x;

    float4 v[16];
    float s = 0.f, s2 = 0.f;
    #pragma unroll
    for (int j = 0; j < 16; j++) {
        float4 a = xp[j * 256 + tid];
        v[j] = a;
        s  += a.x + a.y + a.z + a.w;
        s2 += a.x*a.x + a.y*a.y + a.z*a.z + a.w*a.w;
    }
    block_reduce2(s, s2, sh);
    float mean = s * (1.f / 16384.f);
    float var  = s2 * (1.f / 16384.f) - mean * mean;
    float rstd = rsqrtf(var + EPS_);

    float scl[16], shf[16];
    #pragma unroll
    for (int j = 0; j < 16; j++) {
        int ch = g * 16 + j;
        scl[j] = w[ch] * rstd;
        shf[j] = bia[ch] - mean * scl[j];
    }

    float4* op = (float4*)(g_xn + off);
    #pragma unroll
    for (int j = 0; j < 16; j++) {
        float4 a = v[j], o;
        o.x = a.x * scl[j] + shf[j]; o.y = a.y * scl[j] + shf[j];
        o.z = a.z * scl[j] + shf[j]; o.w = a.w * scl[j] + shf[j];
        v[j] = o;
        op[j * 256 + tid] = o;
    }

    __half* xt = g_xnt + ((size_t)b * TDIM + (size_t)tid * 4) * CDIM + g * 16;
    #pragma unroll
    for (int u = 0; u < 4; u++) {
        uint32_t tmp[8];
        #pragma unroll
        for (int j2 = 0; j2 < 8; j2++)
            tmp[j2] = packhf(((const float*)&v[j2*2])[u],
                             ((const float*)&v[j2*2+1])[u]);
        uint4* r = (uint4*)(xt + (size_t)u * CDIM);
        r[0] = *(uint4*)(tmp);
        r[1] = *(uint4*)(tmp + 4);
    }
}

// ===========================================================================
// f16 mma GEMM (R15 shape: 256 thr, 8 warps 4x2, warp tile 32x64), KC=64,
// 2-stage cp.async, ONE barrier per K-iter (wait -> sync -> load-next -> mma).
// MODE 0: Bt=g_xnt,   out -> g_qkvb (q,v) + g_kt (k transposed), f16
// MODE 1: Bt=g_attnt, out -> g_y = RES_SCALE*g_xn + proj + bias (fp32)
// ===========================================================================
#define KC 64
#define BSTR 72                    // f16 row stride (144 B)
#define GITER (CDIM / KC)          // 8
#define GSTAGE (128 * BSTR)
#define GEMM_SMEM (2 * GSTAGE * 2 * 2)   // 73728 B

template <int MODE>
__global__ __launch_bounds__(256, 2) void mma_gemm(const float* __restrict__ bias,
                                                   int z0)
{
    extern __shared__ __half smg[];
    __half* As = smg;
    __half* Bs = smg + 2 * GSTAGE;

    const int tid  = threadIdx.x;
    const int lane = tid & 31;
    const int wrp  = tid >> 5;
    const int g    = lane >> 2, tig = lane & 3;
    const int m0w  = (wrp & 3) * 32;
    const int n0w  = (wrp >> 2) * 64;

    const int mat = lane >> 3, rowl = lane & 7;
    const uint32_t roffA = ((mat & 1) * 8 + rowl) * 144 + (mat >> 1) * 16;
    const uint32_t roffB = ((mat >> 1) * 8 + rowl) * 144 + (mat & 1) * 16;
    const uint32_t asB = (uint32_t)__cvta_generic_to_shared(As);
    const uint32_t bsB = (uint32_t)__cvta_generic_to_shared(Bs);

    const int z    = blockIdx.z + z0;
    const int row0 = blockIdx.y * 128;
    const int col0 = blockIdx.x * 128;
    const __half* Aw = (MODE == 0 ? g_wqkv : g_wproj) + (size_t)row0 * CDIM;
    const __half* Bb = (MODE == 0 ? g_xnt : g_attnt)
                     + (size_t)z * TDIM * CDIM + (size_t)col0 * CDIM;

    float acc[2][8][4];
    #pragma unroll
    for (int mt = 0; mt < 2; mt++)
        #pragma unroll
        for (int nt = 0; nt < 8; nt++)
            #pragma unroll
            for (int j = 0; j < 4; j++) acc[mt][nt][j] = 0.f;

    auto load_stage = [&](int st, int k0) {
        __half* pa = As + st * GSTAGE;
        __half* pb = Bs + st * GSTAGE;
        #pragma unroll
        for (int s = 0; s < 4; s++) {
            int i = tid + s * 256;
            int row = i >> 3, kc = (i & 7) * 8;
            cp16(pa + row * BSTR + kc, Aw + (size_t)row * CDIM + k0 + kc);
            cp16(pb + row * BSTR + kc, Bb + (size_t)row * CDIM + k0 + kc);
        }
    };

    load_stage(0, 0);  CP_COMMIT();

    #pragma unroll 1
    for (int it = 0; it < GITER; it++) {
        int st = it & 1;
        CP_WAIT0();          // stage st resident (load issued previous iter)
        __syncthreads();     // all warps done reading stage st^1
        if (it + 1 < GITER) {
            load_stage(st ^ 1, (it + 1) * KC);   // overlaps this iter's MMAs
            CP_COMMIT();
        }

        const uint32_t aSt = asB + st * GSTAGE * 2;
        const uint32_t bSt = bsB + st * GSTAGE * 2;
        #pragma unroll
        for (int ks = 0; ks < 4; ks++) {
            uint32_t aF[2][4];
            ldsm_x4(aF[0], aSt + (uint32_t)(m0w)      * 144 + roffA + ks * 32);
            ldsm_x4(aF[1], aSt + (uint32_t)(m0w + 16) * 144 + roffA + ks * 32);
            #pragma unroll
            for (int p = 0; p < 4; p++) {
                uint32_t bF[4];
                ldsm_x4(bF, bSt + (uint32_t)(n0w + p * 16) * 144 + roffB + ks * 32);
                mma_f16(acc[0][2*p],   aF[0], bF);
                mma_f16(acc[0][2*p+1], aF[0], bF + 2);
                mma_f16(acc[1][2*p],   aF[1], bF);
                mma_f16(acc[1][2*p+1], aF[1], bF + 2);
            }
        }
    }

    // Epilogue
    #pragma unroll
    for (int mt = 0; mt < 2; mt++) {
        #pragma unroll
        for (int rr = 0; rr < 2; rr++) {
            int m = row0 + m0w + mt * 16 + g + rr * 8;
            float bv = bias[m];
            if (MODE == 0) {
                int head = m / 192, r = m % 192;
                float scale = (r < 128) ? QK_SCALE_E : 1.f;
                if (r >= 64 && r < 128) {
                    __half* kb = g_kt + (((size_t)(z * 8 + head)) << 10) * 64 + (r - 64);
                    #pragma unroll
                    for (int nt = 0; nt < 8; nt++) {
                        int t = col0 + n0w + nt * 8 + 2 * tig;
                        float x0 = (acc[mt][nt][rr * 2 + 0] + bv) * scale;
                        float x1 = (acc[mt][nt][rr * 2 + 1] + bv) * scale;
                        kb[(size_t)t * 64]       = __float2half(x0);
                        kb[(size_t)(t + 1) * 64] = __float2half(x1);
                    }
                } else {
                    __half* crow = g_qkvb + ((size_t)z * 1536 + m) * TDIM
                                 + col0 + n0w;
                    #pragma unroll
                    for (int nt = 0; nt < 8; nt++) {
                        uint32_t p = packhf((acc[mt][nt][rr*2+0] + bv) * scale,
                                            (acc[mt][nt][rr*2+1] + bv) * scale);
                        *(uint32_t*)(crow + nt * 8 + 2 * tig) = p;
                    }
                }
            } else {
                size_t rowoff = ((size_t)z * CDIM + m) * TDIM + col0 + n0w;
                const float* xnrow = g_xn + rowoff;
                float* crow = g_y + rowoff;
                #pragma unroll
                for (int nt = 0; nt < 8; nt++) {
                    float2 xv = *(const float2*)(xnrow + nt * 8 + 2 * tig);
                    float2 o;
                    o.x = acc[mt][nt][rr * 2 + 0] + bv + RES_SCALE_ * xv.x;
                    o.y = acc[mt][nt][rr * 2 + 1] + bv + RES_SCALE_ * xv.y;
                    *(float2*)(crow + nt * 8 + 2 * tig) = o;
                }
            }
        }
    }
}

// ===========================================================================
// Flash attention (R15): 256-query CTA, warp owns 32 queries (two 16-q
// sub-tiles) sharing each K/V ldmatrix fragment. 4-stage ring, sync per 2
// tiles, f16x2 exp2, l-via-ones-MMA.
// ===========================================================================
#define KST 72                      // f16 row stride (144 B)
#define KVSTAGE (64 * KST)
#define ASTAGES 4
#define ATTN_SMEM (2 * ASTAGES * KVSTAGE * 2)   // 73728 B

__global__ __launch_bounds__(256) void attn_mma_kernel(int bh0)
{
    extern __shared__ __half sma[];
    __half* Ks = sma;                         // 4 stages
    __half* Vs = sma + ASTAGES * KVSTAGE;     // 4 stages

    const int tid  = threadIdx.x;
    const int lane = tid & 31;
    const int wrp  = tid >> 5;
    const int g    = lane >> 2, tig = lane & 3;
    const int ql   = wrp * 32;               // warp query base (32 q)

    const int mat = lane >> 3, rowl = lane & 7;
    const uint32_t roff = ((mat >> 1) * 8 + rowl) * (KST * 2) + (mat & 1) * 16;
    const uint32_t ksB = (uint32_t)__cvta_generic_to_shared(Ks);
    const uint32_t vsB = (uint32_t)__cvta_generic_to_shared(Vs);

    const int bh = blockIdx.y + bh0;
    const int b = bh >> 3, head = bh & 7;
    const int q0 = blockIdx.x * 256;

    const __half* qp  = g_qkvb + ((size_t)b * 1536 + head * 192) * TDIM;
    const __half* vp  = qp + (size_t)128 * TDIM;
    const __half* ktp = g_kt + (((size_t)(b * 8 + head)) << 10) * 64;

    auto load_stage = [&](int st, int s0) {
        __half* pk = Ks + st * KVSTAGE;
        __half* pv = Vs + st * KVSTAGE;
        #pragma unroll
        for (int s = 0; s < 2; s++) {
            int i = tid + s * 256;
            int row = i >> 3, ch8 = (i & 7) * 8;
            cp16(pk + row * KST + ch8, ktp + (size_t)(s0 + row) * 64 + ch8);
            cp16(pv + row * KST + ch8, vp + (size_t)row * TDIM + s0 + ch8);
        }
    };

    // Q fragments for both 16-q sub-tiles, register-resident
    uint32_t aQ[2][4][4];
    #pragma unroll
    for (int s = 0; s < 2; s++) {
        int tq0 = q0 + ql + s * 16 + g;
        #pragma unroll
        for (int kk = 0; kk < 4; kk++) {
            int c0 = kk * 16 + 2 * tig;
            aQ[s][kk][0] = packhf(__half2float(qp[(size_t)(c0)     * TDIM + tq0]),
                                  __half2float(qp[(size_t)(c0 + 1) * TDIM + tq0]));
            aQ[s][kk][1] = packhf(__half2float(qp[(size_t)(c0)     * TDIM + tq0 + 8]),
                                  __half2float(qp[(size_t)(c0 + 1) * TDIM + tq0 + 8]));
            aQ[s][kk][2] = packhf(__half2float(qp[(size_t)(c0 + 8) * TDIM + tq0]),
                                  __half2float(qp[(size_t)(c0 + 9) * TDIM + tq0]));
            aQ[s][kk][3] = packhf(__half2float(qp[(size_t)(c0 + 8) * TDIM + tq0 + 8]),
                                  __half2float(qp[(size_t)(c0 + 9) * TDIM + tq0 + 8]));
        }
    }

    load_stage(0, 0);   CP_COMMIT();
    load_stage(1, 64);  CP_COMMIT();

    float oacc[2][8][4];
    #pragma unroll
    for (int s = 0; s < 2; s++)
        #pragma unroll
        for (int ct = 0; ct < 8; ct++)
            #pragma unroll
            for (int j = 0; j < 4; j++) oacc[s][ct][j] = 0.f;
    float lacc[2][4] = {{0.f,0.f,0.f,0.f},{0.f,0.f,0.f,0.f}};
    float m0[2] = {-1e30f, -1e30f}, m1[2] = {-1e30f, -1e30f};
    const uint32_t ONES2 = 0x3C003C00u;
    uint32_t onesF[2] = {ONES2, ONES2};

    #pragma unroll 1
    for (int kt = 0; kt < 16; kt++) {
        int st = kt % ASTAGES;
        if ((kt & 1) == 0) {
            CP_WAIT0();
            __syncthreads();
        }
        if (kt + 2 < 16) {
            load_stage((kt + 2) % ASTAGES, (kt + 2) * 64);
            CP_COMMIT();
        }

        const uint32_t kSt = ksB + st * KVSTAGE * 2;
        const uint32_t vSt = vsB + st * KVSTAGE * 2;

        // S = Q^T K : [32q][64s]; each K fragment feeds BOTH sub-tiles
        float sacc[2][8][4];
        #pragma unroll
        for (int s = 0; s < 2; s++)
            #pragma unroll
            for (int nt = 0; nt < 8; nt++)
                #pragma unroll
                for (int j = 0; j < 4; j++) sacc[s][nt][j] = 0.f;
        #pragma unroll
        for (int kk = 0; kk < 4; kk++) {
            #pragma unroll
            for (int p = 0; p < 4; p++) {
                uint32_t bF[4];
                ldsm_x4(bF, kSt + p * (16 * KST * 2) + roff + kk * 32);
                mma_f16(sacc[0][2*p],   aQ[0][kk], bF);
                mma_f16(sacc[0][2*p+1], aQ[0][kk], bF + 2);
                mma_f16(sacc[1][2*p],   aQ[1][kk], bF);
                mma_f16(sacc[1][2*p+1], aQ[1][kk], bF + 2);
            }
        }

        // online softmax per sub-tile (exp2 domain)
        #pragma unroll
        for (int s = 0; s < 2; s++) {
            float rmax0 = -1e30f, rmax1 = -1e30f;
            #pragma unroll
            for (int nt = 0; nt < 8; nt++) {
                rmax0 = fmaxf(rmax0, fmaxf(sacc[s][nt][0], sacc[s][nt][1]));
                rmax1 = fmaxf(rmax1, fmaxf(sacc[s][nt][2], sacc[s][nt][3]));
            }
            #pragma unroll
            for (int o = 1; o <= 2; o <<= 1) {
                rmax0 = fmaxf(rmax0, __shfl_xor_sync(0xffffffffu, rmax0, o));
                rmax1 = fmaxf(rmax1, __shfl_xor_sync(0xffffffffu, rmax1, o));
            }
            float mn0 = fmaxf(m0[s], rmax0), mn1 = fmaxf(m1[s], rmax1);
            float corr0 = ex2f(m0[s] - mn0), corr1 = ex2f(m1[s] - mn1);
            m0[s] = mn0; m1[s] = mn1;
            lacc[s][0] *= corr0; lacc[s][2] *= corr1;
            #pragma unroll
            for (int ct = 0; ct < 8; ct++) {
                oacc[s][ct][0] *= corr0; oacc[s][ct][1] *= corr0;
                oacc[s][ct][2] *= corr1; oacc[s][ct][3] *= corr1;
            }
        }

        // O += P V^T; each V fragment feeds BOTH sub-tiles
        #pragma unroll
        for (int kk = 0; kk < 4; kk++) {
            uint32_t aP0[4], aP1[4];
            aP0[0] = h2ex2(sacc[0][2*kk][0]   - m0[0], sacc[0][2*kk][1]   - m0[0]);
            aP0[1] = h2ex2(sacc[0][2*kk][2]   - m1[0], sacc[0][2*kk][3]   - m1[0]);
            aP0[2] = h2ex2(sacc[0][2*kk+1][0] - m0[0], sacc[0][2*kk+1][1] - m0[0]);
            aP0[3] = h2ex2(sacc[0][2*kk+1][2] - m1[0], sacc[0][2*kk+1][3] - m1[0]);
            aP1[0] = h2ex2(sacc[1][2*kk][0]   - m0[1], sacc[1][2*kk][1]   - m0[1]);
            aP1[1] = h2ex2(sacc[1][2*kk][2]   - m1[1], sacc[1][2*kk][3]   - m1[1]);
            aP1[2] = h2ex2(sacc[1][2*kk+1][0] - m0[1], sacc[1][2*kk+1][1] - m0[1]);
            aP1[3] = h2ex2(sacc[1][2*kk+1][2] - m1[1], sacc[1][2*kk+1][3] - m1[1]);
            mma_f16(lacc[0], aP0, onesF);
            mma_f16(lacc[1], aP1, onesF);
            #pragma unroll
            for (int p = 0; p < 4; p++) {
                uint32_t bF[4];
                ldsm_x4(bF, vSt + p * (16 * KST * 2) + roff + kk * 32);
                mma_f16(oacc[0][2*p],   aP0, bF);
                mma_f16(oacc[0][2*p+1], aP0, bF + 2);
                mma_f16(oacc[1][2*p],   aP1, bF);
                mma_f16(oacc[1][2*p+1], aP1, bF + 2);
            }
        }
    }

    // normalize + write both sub-tiles
    #pragma unroll
    for (int s = 0; s < 2; s++) {
        float inv0 = 1.f / lacc[s][0], inv1 = 1.f / lacc[s][2];
        int tq = q0 + ql + s * 16 + g;
        __half* orow0 = g_attnt + ((size_t)b * TDIM + tq)     * CDIM + head * 64;
        __half* orow1 = g_attnt + ((size_t)b * TDIM + tq + 8) * CDIM + head * 64;
        #pragma unroll
        for (int ct = 0; ct < 8; ct++) {
            *(uint32_t*)(orow0 + ct * 8 + 2 * tig) =
                packhf(oacc[s][ct][0] * inv0, oacc[s][ct][1] * inv0);
            *(uint32_t*)(orow1 + ct * 8 + 2 * tig) =
                packhf(oacc[s][ct][2] * inv1, oacc[s][ct][3] * inv1);
        }
    }
}

// ===========================================================================
// GroupNorm #2 (no affine) over g_y -> d_out. blk0: block offset.
// ===========================================================================
__global__ __launch_bounds__(256) void gn2_kernel(float* __restrict__ out, int blk0)
{
    __shared__ float sh[16];
    int blk = blockIdx.x + blk0;
    int b = blk >> 5, g = blk & 31;
    size_t off = ((size_t)b * CDIM + (size_t)g * 16) * TDIM;
    const float4* yp = (const float4*)(g_y + off);
    int tid = threadIdx.x;

    float4 v[16];
    float s = 0.f, s2 = 0.f;
    #pragma unroll
    for (int j = 0; j < 16; j++) {
        float4 y = yp[j * 256 + tid];
        v[j] = y;
        s  += y.x + y.y + y.z + y.w;
        s2 += y.x*y.x + y.y*y.y + y.z*y.z + y.w*y.w;
    }
    block_reduce2(s, s2, sh);
    float mean = s * (1.f / 16384.f);
    float var  = s2 * (1.f / 16384.f) - mean * mean;
    float rstd = rsqrtf(var + EPS_);

    float4* op = (float4*)(out + off);
    #pragma unroll
    for (int j = 0; j < 16; j++) {
        float4 y = v[j], o;
        o.x = (y.x - mean) * rstd; o.y = (y.y - mean) * rstd;
        o.z = (y.z - mean) * rstd; o.w = (y.w - mean) * rstd;
        op[j * 256 + tid] = o;
    }
}

// ===========================================================================
extern "C" void kernel_launch(void* const* d_in, const int* in_sizes, int n_in,
                              void* d_out, int out_size)
{
    const float* x      = (const float*)d_in[0];
    const float* gn_w   = (const float*)d_in[1];
    const float* gn_b   = (const float*)d_in[2];
    const float* qkv_w  = (const float*)d_in[3];
    const float* qkv_b  = (const float*)d_in[4];
    const float* proj_w = (const float*)d_in[5];
    const float* proj_b = (const float*)d_in[6];
    float* out = (float*)d_out;

    cudaFuncSetAttribute(mma_gemm<0>, cudaFuncAttributeMaxDynamicSharedMemorySize, GEMM_SMEM);
    cudaFuncSetAttribute(mma_gemm<1>, cudaFuncAttributeMaxDynamicSharedMemorySize, GEMM_SMEM);
    cudaFuncSetAttribute(attn_mma_kernel, cudaFuncAttributeMaxDynamicSharedMemorySize, ATTN_SMEM);

    const int WQ = (1536 * CDIM / 4 + 255) / 256;
    const int WP = (CDIM * CDIM / 4 + 255) / 256;

    if (g_rig.ok) {
        cudaStream_t sH = g_rig.sH, sL = g_rig.sL;
        // fork from capture (legacy) stream
        cudaEventRecord(g_rig.e0, 0);
        cudaStreamWaitEvent(sH, g_rig.e0, 0);
        cudaStreamWaitEvent(sL, g_rig.e0, 0);

        // chain B: qkv weights first (critical), then proj weights, gn1B
        wconv_qkv_kernel<<<WQ, 256, 0, sL>>>(qkv_w);
        cudaEventRecord(g_rig.eW, sL);
        wconv_proj_kernel<<<WP, 256, 0, sL>>>(proj_w);
        cudaEventRecord(g_rig.eW2, sL);
        gn1_kernel<<<128, 256, 0, sL>>>(x, gn_w, gn_b, 128);  // batches 4-7

        // chain A: gn1A -> qkvA -> attnA -> projA -> gn2A
        gn1_kernel<<<128, 256, 0, sH>>>(x, gn_w, gn_b, 0);    // batches 0-3
        cudaStreamWaitEvent(sH, g_rig.eW, 0);                 // qkv weights ready
        mma_gemm<0><<<dim3(8, 12, 4), 256, GEMM_SMEM, sH>>>(qkv_b, 0);
        attn_mma_kernel<<<dim3(4, 32), 256, ATTN_SMEM, sH>>>(0);
        cudaStreamWaitEvent(sH, g_rig.eW2, 0);                // proj weights ready
        mma_gemm<1><<<dim3(8, 4, 4), 256, GEMM_SMEM, sH>>>(proj_b, 0);
        gn2_kernel<<<128, 256, 0, sH>>>(out, 0);
        cudaEventRecord(g_rig.eA, sH);

        // chain B continues (fully concurrent with chain A)
        mma_gemm<0><<<dim3(8, 12, 4), 256, GEMM_SMEM, sL>>>(qkv_b, 4);
        attn_mma_kernel<<<dim3(4, 32), 256, ATTN_SMEM, sL>>>(32);
        mma_gemm<1><<<dim3(8, 4, 4), 256, GEMM_SMEM, sL>>>(proj_b, 4);
        gn2_kernel<<<128, 256, 0, sL>>>(out, 128);
        cudaEventRecord(g_rig.eB, sL);

        // rejoin capture stream
        cudaStreamWaitEvent((cudaStream_t)0, g_rig.eA, 0);
        cudaStreamWaitEvent((cudaStream_t)0, g_rig.eB, 0);
    } else {
        // serial fallback
        wconv_qkv_kernel<<<WQ, 256>>>(qkv_w);
        wconv_proj_kernel<<<WP, 256>>>(proj_w);
        gn1_kernel<<<BATCH * 32, 256>>>(x, gn_w, gn_b, 0);
        mma_gemm<0><<<dim3(8, 12, 8), 256, GEMM_SMEM>>>(qkv_b, 0);
        attn_mma_kernel<<<dim3(4, 64), 256, ATTN_SMEM>>>(0);
        mma_gemm<1><<<dim3(8, 4, 8), 256, GEMM_SMEM>>>(proj_b, 0);
        gn2_kernel<<<256, 256>>>(out, 0);
    }
}